// round 1
// baseline (speedup 1.0000x reference)
#include <cuda_runtime.h>
#include <math.h>

// ---------------- problem constants ----------------
#define BATCH   8
#define CDIM    384
#define HW      1024            // 32*32 tokens per image
#define NTOK    (BATCH * HW)    // 8192
#define HEADS   8
#define DH      48              // 384 / 8
#define D3      (3 * CDIM)      // 1152
#define DFF     (4 * CDIM)      // 1536
#define EPSLN   1e-5f

// ---------------- scratch (device globals; no allocation allowed) ----------------
__device__ float g_t  [NTOK * CDIM];   // tokens (residual stream)
__device__ float g_a  [NTOK * CDIM];   // double-LN output
__device__ float g_qkv[NTOK * D3];
__device__ float g_o  [NTOK * CDIM];   // attention output (pre-projection)
__device__ float g_t2 [NTOK * CDIM];   // after attention residual
__device__ float g_m  [NTOK * CDIM];   // LN2 output
__device__ float g_h  [NTOK * DFF];    // MLP hidden
__device__ float g_t3 [NTOK * CDIM];   // final tokens

// ---------------- input transpose: x[B][C][HW] -> t[(b*HW+n)][C] ----------------
__global__ void transpose_in_kernel(const float* __restrict__ x, float* __restrict__ t) {
    __shared__ float tile[32][33];
    const int b  = blockIdx.z;
    const int c0 = blockIdx.y * 32;
    const int n0 = blockIdx.x * 32;
    const int tx = threadIdx.x;
    #pragma unroll
    for (int i = threadIdx.y; i < 32; i += 8)
        tile[i][tx] = x[(size_t)b * CDIM * HW + (size_t)(c0 + i) * HW + n0 + tx];
    __syncthreads();
    #pragma unroll
    for (int i = threadIdx.y; i < 32; i += 8)
        t[(size_t)(b * HW + n0 + i) * CDIM + c0 + tx] = tile[tx][i];
}

// ---------------- output transpose: t3[(b*HW+n)][C] -> out[B][C][HW] ----------------
__global__ void transpose_out_kernel(const float* __restrict__ t3, float* __restrict__ out) {
    __shared__ float tile[32][33];
    const int b  = blockIdx.z;
    const int c0 = blockIdx.y * 32;
    const int n0 = blockIdx.x * 32;
    const int tx = threadIdx.x;
    #pragma unroll
    for (int i = threadIdx.y; i < 32; i += 8)
        tile[i][tx] = t3[(size_t)(b * HW + n0 + i) * CDIM + c0 + tx];
    __syncthreads();
    #pragma unroll
    for (int i = threadIdx.y; i < 32; i += 8)
        out[(size_t)b * CDIM * HW + (size_t)(c0 + i) * HW + n0 + tx] = tile[tx][i];
}

// ---------------- block reduction (128 threads) ----------------
__device__ __forceinline__ float blockSum128(float v) {
    __shared__ float sh[4];
    #pragma unroll
    for (int o = 16; o > 0; o >>= 1) v += __shfl_xor_sync(0xffffffffu, v, o);
    if ((threadIdx.x & 31) == 0) sh[threadIdx.x >> 5] = v;
    __syncthreads();
    float r = sh[0] + sh[1] + sh[2] + sh[3];
    __syncthreads();
    return r;
}

// ---------------- layernorm: one token row per block (128 threads, 3 elems/thread) ----------------
// dbl=1: apply (g1,b1) then (g2,b2) (the double pre-norm); dbl=0: single LN with (g1,b1)
__global__ __launch_bounds__(128) void ln_kernel(
    const float* __restrict__ in, float* __restrict__ out,
    const float* __restrict__ g1, const float* __restrict__ b1,
    const float* __restrict__ g2, const float* __restrict__ b2, int dbl)
{
    const int row = blockIdx.x;
    const float* p = in + (size_t)row * CDIM;
    float v[3];
    #pragma unroll
    for (int i = 0; i < 3; i++) v[i] = p[threadIdx.x + i * 128];

    float s = blockSum128(v[0] + v[1] + v[2]);
    float mu = s * (1.0f / CDIM);
    float sq = 0.f;
    #pragma unroll
    for (int i = 0; i < 3; i++) { float d = v[i] - mu; sq += d * d; }
    float var = blockSum128(sq) * (1.0f / CDIM);
    float rs = rsqrtf(var + EPSLN);
    #pragma unroll
    for (int i = 0; i < 3; i++) {
        int c = threadIdx.x + i * 128;
        v[i] = (v[i] - mu) * rs * g1[c] + b1[c];
    }
    if (dbl) {
        float s2 = blockSum128(v[0] + v[1] + v[2]);
        float mu2 = s2 * (1.0f / CDIM);
        float sq2 = 0.f;
        #pragma unroll
        for (int i = 0; i < 3; i++) { float d = v[i] - mu2; sq2 += d * d; }
        float var2 = blockSum128(sq2) * (1.0f / CDIM);
        float rs2 = rsqrtf(var2 + EPSLN);
        #pragma unroll
        for (int i = 0; i < 3; i++) {
            int c = threadIdx.x + i * 128;
            v[i] = (v[i] - mu2) * rs2 * g2[c] + b2[c];
        }
    }
    #pragma unroll
    for (int i = 0; i < 3; i++) out[(size_t)row * CDIM + threadIdx.x + i * 128] = v[i];
}

// ---------------- SGEMM 128x128x8, 256 threads, 8x8 micro-tile ----------------
// epi: 0 = none; 1 = +res; 2 = +bias then exact GELU; 3 = +bias +res
__global__ __launch_bounds__(256) void sgemm128(
    const float* __restrict__ A, const float* __restrict__ Bm, float* __restrict__ C,
    const float* __restrict__ bias, const float* __restrict__ res,
    int M, int N, int K, int epi)
{
    __shared__ float As[8][128];
    __shared__ float Bs[8][128];
    const int tid  = threadIdx.x;
    const int row0 = blockIdx.y * 128;
    const int col0 = blockIdx.x * 128;

    const int arow = tid >> 1;          // 0..127
    const int acol = (tid & 1) * 4;     // 0 or 4
    const int brl  = tid >> 5;          // 0..7
    const int bcl  = (tid & 31) * 4;    // 0..124
    const int tx   = (tid & 15) * 8;
    const int ty   = (tid >> 4) * 8;

    float acc[8][8];
    #pragma unroll
    for (int i = 0; i < 8; i++)
        #pragma unroll
        for (int j = 0; j < 8; j++) acc[i][j] = 0.f;

    const float* Aptr = A + (size_t)(row0 + arow) * K + acol;
    const float* Bptr = Bm + (size_t)brl * N + col0 + bcl;

    for (int k0 = 0; k0 < K; k0 += 8) {
        float4 av = *(const float4*)(Aptr + k0);
        float4 bv = *(const float4*)(Bptr + (size_t)k0 * N);
        As[acol + 0][arow] = av.x;
        As[acol + 1][arow] = av.y;
        As[acol + 2][arow] = av.z;
        As[acol + 3][arow] = av.w;
        *(float4*)&Bs[brl][bcl] = bv;
        __syncthreads();
        #pragma unroll
        for (int k = 0; k < 8; k++) {
            float ar[8], br[8];
            #pragma unroll
            for (int i = 0; i < 8; i++) ar[i] = As[k][ty + i];
            #pragma unroll
            for (int j = 0; j < 8; j++) br[j] = Bs[k][tx + j];
            #pragma unroll
            for (int i = 0; i < 8; i++)
                #pragma unroll
                for (int j = 0; j < 8; j++)
                    acc[i][j] = fmaf(ar[i], br[j], acc[i][j]);
        }
        __syncthreads();
    }

    #pragma unroll
    for (int i = 0; i < 8; i++) {
        const int r = row0 + ty + i;
        #pragma unroll
        for (int j = 0; j < 8; j++) {
            const int c = col0 + tx + j;
            float v = acc[i][j];
            if (epi == 1) {
                v += res[(size_t)r * N + c];
            } else if (epi == 2) {
                v += bias[c];
                v = 0.5f * v * (1.0f + erff(v * 0.70710678118654752f));
            } else if (epi == 3) {
                v += bias[c] + res[(size_t)r * N + c];
            }
            C[(size_t)r * N + c] = v;
        }
    }
}

// ---------------- attention: one thread = one query; flash-style online softmax ----------------
__global__ __launch_bounds__(128) void attn_kernel(
    const float* __restrict__ qkv, float* __restrict__ o)
{
    __shared__ float Ks[32][48];
    __shared__ float Vs[32][48];
    const int bh = blockIdx.x;                 // 0..63
    const int b = bh >> 3, h = bh & 7;
    const int qi = blockIdx.y * 128 + threadIdx.x;   // 0..1023
    const int tokBase = b * HW;
    const float scale = 0.14433756729740645f;  // 1/sqrt(48)

    const float* qptr = qkv + (size_t)(tokBase + qi) * D3 + h * DH;
    float q[48];
    #pragma unroll
    for (int c = 0; c < 48; c++) q[c] = qptr[c];

    float oacc[48];
    #pragma unroll
    for (int c = 0; c < 48; c++) oacc[c] = 0.f;
    float mrun = -1e30f, lrun = 0.f;

    for (int kk = 0; kk < HW; kk += 32) {
        __syncthreads();
        for (int idx = threadIdx.x; idx < 32 * 48; idx += 128) {
            int j = idx / 48, c = idx % 48;
            size_t base = (size_t)(tokBase + kk + j) * D3 + h * DH;
            Ks[j][c] = qkv[base + CDIM + c];        // K block
            Vs[j][c] = qkv[base + 2 * CDIM + c];    // V block
        }
        __syncthreads();

        for (int g = 0; g < 4; g++) {
            float sc[8];
            #pragma unroll
            for (int j = 0; j < 8; j++) {
                float s = 0.f;
                #pragma unroll
                for (int c = 0; c < 48; c++) s = fmaf(q[c], Ks[g * 8 + j][c], s);
                sc[j] = s * scale;
            }
            float gm = sc[0];
            #pragma unroll
            for (int j = 1; j < 8; j++) gm = fmaxf(gm, sc[j]);
            float newm = fmaxf(mrun, gm);
            float corr = __expf(mrun - newm);
            lrun *= corr;
            #pragma unroll
            for (int c = 0; c < 48; c++) oacc[c] *= corr;
            mrun = newm;
            #pragma unroll
            for (int j = 0; j < 8; j++) {
                float p = __expf(sc[j] - newm);
                lrun += p;
                #pragma unroll
                for (int c = 0; c < 48; c++) oacc[c] = fmaf(p, Vs[g * 8 + j][c], oacc[c]);
            }
        }
    }

    float inv = 1.0f / lrun;
    float* optr = o + (size_t)(tokBase + qi) * CDIM + h * DH;
    #pragma unroll
    for (int c = 0; c < 48; c++) optr[c] = oacc[c] * inv;
}

// ---------------- launch ----------------
extern "C" void kernel_launch(void* const* d_in, const int* in_sizes, int n_in,
                              void* d_out, int out_size)
{
    const float* x     = (const float*)d_in[0];
    const float* ln1_g = (const float*)d_in[1];
    const float* ln1_b = (const float*)d_in[2];
    const float* lna_g = (const float*)d_in[3];
    const float* lna_b = (const float*)d_in[4];
    const float* w_qkv = (const float*)d_in[5];
    const float* w_out = (const float*)d_in[6];
    const float* ln2_g = (const float*)d_in[7];
    const float* ln2_b = (const float*)d_in[8];
    const float* w1    = (const float*)d_in[9];
    const float* b1    = (const float*)d_in[10];
    const float* w2    = (const float*)d_in[11];
    const float* b2    = (const float*)d_in[12];
    float* out = (float*)d_out;

    float *t, *a, *qkvb, *ob, *t2, *mb, *hb, *t3;
    cudaGetSymbolAddress((void**)&t,    g_t);
    cudaGetSymbolAddress((void**)&a,    g_a);
    cudaGetSymbolAddress((void**)&qkvb, g_qkv);
    cudaGetSymbolAddress((void**)&ob,   g_o);
    cudaGetSymbolAddress((void**)&t2,   g_t2);
    cudaGetSymbolAddress((void**)&mb,   g_m);
    cudaGetSymbolAddress((void**)&hb,   g_h);
    cudaGetSymbolAddress((void**)&t3,   g_t3);

    dim3 tblk(32, 8);
    dim3 tgrid(HW / 32, CDIM / 32, BATCH);

    // 1. x -> token-major t
    transpose_in_kernel<<<tgrid, tblk>>>(x, t);
    // 2. double pre-norm -> a
    ln_kernel<<<NTOK, 128>>>(t, a, ln1_g, ln1_b, lna_g, lna_b, 1);
    // 3. qkv = a @ w_qkv
    sgemm128<<<dim3(D3 / 128, NTOK / 128), 256>>>(a, w_qkv, qkvb, nullptr, nullptr, NTOK, D3, CDIM, 0);
    // 4. attention -> o
    attn_kernel<<<dim3(BATCH * HEADS, HW / 128), 128>>>(qkvb, ob);
    // 5. t2 = t + o @ w_out
    sgemm128<<<dim3(CDIM / 128, NTOK / 128), 256>>>(ob, w_out, t2, nullptr, t, NTOK, CDIM, CDIM, 1);
    // 6. m = LN2(t2)
    ln_kernel<<<NTOK, 128>>>(t2, mb, ln2_g, ln2_b, nullptr, nullptr, 0);
    // 7. h = gelu(m @ w1 + b1)
    sgemm128<<<dim3(DFF / 128, NTOK / 128), 256>>>(mb, w1, hb, b1, nullptr, NTOK, DFF, CDIM, 2);
    // 8. t3 = t2 + h @ w2 + b2
    sgemm128<<<dim3(CDIM / 128, NTOK / 128), 256>>>(hb, w2, t3, b2, t2, NTOK, CDIM, DFF, 3);
    // 9. t3 -> NCHW output
    transpose_out_kernel<<<tgrid, tblk>>>(t3, out);
}

// round 3
// speedup vs baseline: 1.9310x; 1.9310x over previous
#include <cuda_runtime.h>
#include <cuda_fp16.h>
#include <math.h>
#include <stdint.h>

// ---------------- problem constants ----------------
#define BATCH   8
#define CDIM    384
#define HW      1024
#define NTOK    (BATCH * HW)    // 8192
#define HEADS   8
#define DH      48
#define D3      (3 * CDIM)      // 1152
#define DFF     (4 * CDIM)      // 1536
#define EPSLN   1e-5f

// ---------------- scratch ----------------
__device__ float  g_t  [NTOK * CDIM];
__device__ __half g_ah [NTOK * CDIM];
__device__ float  g_qkv[NTOK * D3];
__device__ __half g_oh [NTOK * CDIM];
__device__ float  g_t2 [NTOK * CDIM];
__device__ __half g_mh [NTOK * CDIM];
__device__ __half g_hh [NTOK * DFF];
__device__ float  g_t3 [NTOK * CDIM];
__device__ __half g_wqkvT[D3 * CDIM];     // [N,K] fp16
__device__ __half g_woutT[CDIM * CDIM];
__device__ __half g_w1T  [DFF * CDIM];
__device__ __half g_w2T  [CDIM * DFF];

// ---------------- small helpers ----------------
__device__ __forceinline__ uint32_t smem_u32(const void* p) {
    uint32_t a;
    asm("{ .reg .u64 t; cvta.to.shared.u64 t, %1; cvt.u32.u64 %0, t; }" : "=r"(a) : "l"(p));
    return a;
}
__device__ __forceinline__ void cp_async16(uint32_t s, const void* g) {
    asm volatile("cp.async.cg.shared.global [%0], [%1], 16;" :: "r"(s), "l"(g));
}
#define CP_COMMIT() asm volatile("cp.async.commit_group;" ::: "memory")
#define CP_WAIT0()  asm volatile("cp.async.wait_group 0;" ::: "memory")

__device__ __forceinline__ void ldmatrix4(uint32_t* r, uint32_t addr) {
    asm volatile("ldmatrix.sync.aligned.m8n8.x4.shared.b16 {%0,%1,%2,%3}, [%4];"
        : "=r"(r[0]), "=r"(r[1]), "=r"(r[2]), "=r"(r[3]) : "r"(addr));
}
__device__ __forceinline__ void mma16816(float* c, const uint32_t* a, const uint32_t* b) {
    asm volatile("mma.sync.aligned.m16n8k16.row.col.f32.f16.f16.f32 "
        "{%0,%1,%2,%3}, {%4,%5,%6,%7}, {%8,%9}, {%0,%1,%2,%3};"
        : "+f"(c[0]), "+f"(c[1]), "+f"(c[2]), "+f"(c[3])
        : "r"(a[0]), "r"(a[1]), "r"(a[2]), "r"(a[3]), "r"(b[0]), "r"(b[1]));
}

// swizzled smem offset for a 128-row x 32-half (64B) tile stored as 64 lines x 128B.
// r: logical row 0..127, g: 16-byte group 0..3 along k.
__device__ __forceinline__ uint32_t swz(uint32_t r, uint32_t g) {
    uint32_t line  = r >> 1;
    uint32_t chunk = (((r & 1u) * 4u + g) ^ (line & 7u));
    return line * 128u + chunk * 16u;
}

// ---------------- transposes ----------------
__global__ void transpose_in_kernel(const float* __restrict__ x, float* __restrict__ t) {
    __shared__ float tile[32][33];
    const int b = blockIdx.z, c0 = blockIdx.y * 32, n0 = blockIdx.x * 32, tx = threadIdx.x;
    #pragma unroll
    for (int i = threadIdx.y; i < 32; i += 8)
        tile[i][tx] = x[(size_t)b * CDIM * HW + (size_t)(c0 + i) * HW + n0 + tx];
    __syncthreads();
    #pragma unroll
    for (int i = threadIdx.y; i < 32; i += 8)
        t[(size_t)(b * HW + n0 + i) * CDIM + c0 + tx] = tile[tx][i];
}

__global__ void transpose_out_kernel(const float* __restrict__ t3, float* __restrict__ out) {
    __shared__ float tile[32][33];
    const int b = blockIdx.z, c0 = blockIdx.y * 32, n0 = blockIdx.x * 32, tx = threadIdx.x;
    #pragma unroll
    for (int i = threadIdx.y; i < 32; i += 8)
        tile[i][tx] = t3[(size_t)(b * HW + n0 + i) * CDIM + c0 + tx];
    __syncthreads();
    #pragma unroll
    for (int i = threadIdx.y; i < 32; i += 8)
        out[(size_t)b * CDIM * HW + (size_t)(c0 + i) * HW + n0 + tx] = tile[tx][i];
}

// weight prep: fp32 [K,N] -> fp16 [N,K]
__global__ void wprep_kernel(const float* __restrict__ w, __half* __restrict__ wt, int K, int N) {
    __shared__ float tile[32][33];
    const int k0 = blockIdx.y * 32, n0 = blockIdx.x * 32, tx = threadIdx.x;
    #pragma unroll
    for (int i = threadIdx.y; i < 32; i += 8)
        tile[i][tx] = w[(size_t)(k0 + i) * N + n0 + tx];
    __syncthreads();
    #pragma unroll
    for (int i = threadIdx.y; i < 32; i += 8)
        wt[(size_t)(n0 + i) * K + k0 + tx] = __float2half_rn(tile[tx][i]);
}

// ---------------- block reduce ----------------
__device__ __forceinline__ float blockSum128(float v) {
    __shared__ float sh[4];
    #pragma unroll
    for (int o = 16; o > 0; o >>= 1) v += __shfl_xor_sync(0xffffffffu, v, o);
    if ((threadIdx.x & 31) == 0) sh[threadIdx.x >> 5] = v;
    __syncthreads();
    float r = sh[0] + sh[1] + sh[2] + sh[3];
    __syncthreads();
    return r;
}

// ---------------- layernorm (fp16 output) ----------------
__global__ __launch_bounds__(128) void ln_kernel(
    const float* __restrict__ in, __half* __restrict__ out,
    const float* __restrict__ g1, const float* __restrict__ b1,
    const float* __restrict__ g2, const float* __restrict__ b2, int dbl)
{
    const int row = blockIdx.x;
    const float* p = in + (size_t)row * CDIM;
    float v[3];
    #pragma unroll
    for (int i = 0; i < 3; i++) v[i] = p[threadIdx.x + i * 128];

    float mu = blockSum128(v[0] + v[1] + v[2]) * (1.0f / CDIM);
    float sq = 0.f;
    #pragma unroll
    for (int i = 0; i < 3; i++) { float d = v[i] - mu; sq += d * d; }
    float rs = rsqrtf(blockSum128(sq) * (1.0f / CDIM) + EPSLN);
    #pragma unroll
    for (int i = 0; i < 3; i++) {
        int c = threadIdx.x + i * 128;
        v[i] = (v[i] - mu) * rs * g1[c] + b1[c];
    }
    if (dbl) {
        float mu2 = blockSum128(v[0] + v[1] + v[2]) * (1.0f / CDIM);
        float sq2 = 0.f;
        #pragma unroll
        for (int i = 0; i < 3; i++) { float d = v[i] - mu2; sq2 += d * d; }
        float rs2 = rsqrtf(blockSum128(sq2) * (1.0f / CDIM) + EPSLN);
        #pragma unroll
        for (int i = 0; i < 3; i++) {
            int c = threadIdx.x + i * 128;
            v[i] = (v[i] - mu2) * rs2 * g2[c] + b2[c];
        }
    }
    #pragma unroll
    for (int i = 0; i < 3; i++)
        out[(size_t)row * CDIM + threadIdx.x + i * 128] = __float2half_rn(v[i]);
}

// ================= HMMA GEMM: 128x128 block, BK=32, 8 warps (4m x 2n), warp = 32x64 ====
// A: [M,K] fp16 row-major; B: [N,K] fp16 row-major (so mma row.col works directly).
// epi: 0 -> Cf = acc; 1 -> Cf = acc + res; 2 -> Ch = half(gelu(acc + bias)); 3 -> Cf = acc+bias+res
__global__ __launch_bounds__(256) void hgemm_mma(
    const __half* __restrict__ A, const __half* __restrict__ B,
    float* __restrict__ Cf, __half* __restrict__ Ch,
    const float* __restrict__ bias, const float* __restrict__ res,
    int N, int K, int epi)
{
    __shared__ __align__(16) __half As[2][128 * 32];
    __shared__ __align__(16) __half Bs[2][128 * 32];

    const int tid = threadIdx.x;
    const int wid = tid >> 5, lid = tid & 31;
    const int row0 = blockIdx.y * 128, col0 = blockIdx.x * 128;
    const int wm = wid & 3;          // M position (32 rows)
    const int wn = wid >> 2;         // N position (64 cols)

    const uint32_t sA = smem_u32(As);
    const uint32_t sB = smem_u32(Bs);

    // ldmatrix per-lane base offsets (kh=0); kh=1 = offset ^ 32
    const uint32_t rowA = ((lid >> 3) & 1) * 8 + (lid & 7);
    const uint32_t kgA  = (uint32_t)lid >> 4;
    uint32_t aoff[2];
    #pragma unroll
    for (int mt = 0; mt < 2; mt++)
        aoff[mt] = swz(wm * 32 + mt * 16 + rowA, kgA);
    const uint32_t rowB = ((lid >> 4) & 1) * 8 + (lid & 7);
    const uint32_t kgB  = (lid >> 3) & 1;
    uint32_t boff[4];
    #pragma unroll
    for (int nt2 = 0; nt2 < 4; nt2++)
        boff[nt2] = swz(wn * 64 + nt2 * 16 + rowB, kgB);

    float acc[2][8][4];
    #pragma unroll
    for (int i = 0; i < 2; i++)
        #pragma unroll
        for (int j = 0; j < 8; j++)
            #pragma unroll
            for (int q = 0; q < 4; q++) acc[i][j][q] = 0.f;

    const int nc = K >> 5;   // K / 32

    // prologue: load chunk 0
    #pragma unroll
    for (int i = 0; i < 2; i++) {
        int v = tid + i * 256;
        int r = v >> 2, g = v & 3;
        uint32_t so = swz(r, g);
        cp_async16(sA + so, A + (size_t)(row0 + r) * K + g * 8);
        cp_async16(sB + so, B + (size_t)(col0 + r) * K + g * 8);
    }
    CP_COMMIT();

    for (int c = 0; c < nc; c++) {
        CP_WAIT0();
        __syncthreads();
        if (c + 1 < nc) {
            const uint32_t bufo = ((c + 1) & 1) * 8192u;
            const int kb = (c + 1) * 32;
            #pragma unroll
            for (int i = 0; i < 2; i++) {
                int v = tid + i * 256;
                int r = v >> 2, g = v & 3;
                uint32_t so = swz(r, g) + bufo;
                cp_async16(sA + so, A + (size_t)(row0 + r) * K + kb + g * 8);
                cp_async16(sB + so, B + (size_t)(col0 + r) * K + kb + g * 8);
            }
            CP_COMMIT();
        }
        const uint32_t bufc = (c & 1) * 8192u;
        #pragma unroll
        for (int kh = 0; kh < 2; kh++) {
            const uint32_t kx = kh * 32u;
            uint32_t a[2][4], b[4][4];
            #pragma unroll
            for (int mt = 0; mt < 2; mt++)
                ldmatrix4(a[mt], sA + bufc + (aoff[mt] ^ kx));
            #pragma unroll
            for (int nt2 = 0; nt2 < 4; nt2++)
                ldmatrix4(b[nt2], sB + bufc + (boff[nt2] ^ kx));
            #pragma unroll
            for (int mt = 0; mt < 2; mt++)
                #pragma unroll
                for (int nt = 0; nt < 8; nt++)
                    mma16816(acc[mt][nt], a[mt], &b[nt >> 1][(nt & 1) * 2]);
        }
    }

    // epilogue
    const int gid = lid >> 2, tig = lid & 3;
    #pragma unroll
    for (int mt = 0; mt < 2; mt++) {
        #pragma unroll
        for (int nt = 0; nt < 8; nt++) {
            const int cc = col0 + wn * 64 + nt * 8 + tig * 2;
            #pragma unroll
            for (int half = 0; half < 2; half++) {
                const int r = row0 + wm * 32 + mt * 16 + gid + half * 8;
                float v0 = acc[mt][nt][half * 2 + 0];
                float v1 = acc[mt][nt][half * 2 + 1];
                if (epi == 1) {
                    v0 += res[(size_t)r * N + cc];
                    v1 += res[(size_t)r * N + cc + 1];
                } else if (epi == 2) {
                    v0 += bias[cc];     v1 += bias[cc + 1];
                    v0 = 0.5f * v0 * (1.0f + erff(v0 * 0.70710678118654752f));
                    v1 = 0.5f * v1 * (1.0f + erff(v1 * 0.70710678118654752f));
                } else if (epi == 3) {
                    v0 += bias[cc] + res[(size_t)r * N + cc];
                    v1 += bias[cc + 1] + res[(size_t)r * N + cc + 1];
                }
                if (epi == 2) {
                    __half2 h2 = __floats2half2_rn(v0, v1);
                    *(__half2*)&Ch[(size_t)r * N + cc] = h2;
                } else {
                    float2 f2 = make_float2(v0, v1);
                    *(float2*)&Cf[(size_t)r * N + cc] = f2;
                }
            }
        }
    }
}

// ---------------- attention (fp32 math, float4 smem reads, fp16 out) ----------------
__global__ __launch_bounds__(128) void attn_kernel(
    const float* __restrict__ qkv, __half* __restrict__ o)
{
    __shared__ __align__(16) float Ks[32][48];
    __shared__ __align__(16) float Vs[32][48];
    const int bh = blockIdx.x;
    const int b = bh >> 3, h = bh & 7;
    const int qi = blockIdx.y * 128 + threadIdx.x;
    const int tokBase = b * HW;
    const float scale = 0.14433756729740645f;

    const float4* qp = (const float4*)(qkv + (size_t)(tokBase + qi) * D3 + h * DH);
    float4 q4[12];
    #pragma unroll
    for (int i = 0; i < 12; i++) q4[i] = qp[i];

    float4 o4[12];
    #pragma unroll
    for (int i = 0; i < 12; i++) o4[i] = make_float4(0.f, 0.f, 0.f, 0.f);
    float mrun = -1e30f, lrun = 0.f;

    for (int kk = 0; kk < HW; kk += 32) {
        __syncthreads();
        for (int idx = threadIdx.x; idx < 32 * 12; idx += 128) {
            int j = idx / 12, f = idx % 12;
            const float4* kb = (const float4*)(qkv + (size_t)(tokBase + kk + j) * D3 + h * DH + CDIM);
            const float4* vb = (const float4*)(qkv + (size_t)(tokBase + kk + j) * D3 + h * DH + 2 * CDIM);
            ((float4*)Ks[j])[f] = kb[f];
            ((float4*)Vs[j])[f] = vb[f];
        }
        __syncthreads();

        for (int g = 0; g < 4; g++) {
            float sc[8];
            #pragma unroll
            for (int j = 0; j < 8; j++) {
                const float4* kr = (const float4*)Ks[g * 8 + j];
                float s = 0.f;
                #pragma unroll
                for (int i = 0; i < 12; i++) {
                    float4 kv = kr[i];
                    s = fmaf(q4[i].x, kv.x, s);
                    s = fmaf(q4[i].y, kv.y, s);
                    s = fmaf(q4[i].z, kv.z, s);
                    s = fmaf(q4[i].w, kv.w, s);
                }
                sc[j] = s * scale;
            }
            float gm = sc[0];
            #pragma unroll
            for (int j = 1; j < 8; j++) gm = fmaxf(gm, sc[j]);
            float newm = fmaxf(mrun, gm);
            float corr = __expf(mrun - newm);
            lrun *= corr;
            #pragma unroll
            for (int i = 0; i < 12; i++) {
                o4[i].x *= corr; o4[i].y *= corr; o4[i].z *= corr; o4[i].w *= corr;
            }
            mrun = newm;
            #pragma unroll
            for (int j = 0; j < 8; j++) {
                float p = __expf(sc[j] - newm);
                lrun += p;
                const float4* vr = (const float4*)Vs[g * 8 + j];
                #pragma unroll
                for (int i = 0; i < 12; i++) {
                    float4 vv = vr[i];
                    o4[i].x = fmaf(p, vv.x, o4[i].x);
                    o4[i].y = fmaf(p, vv.y, o4[i].y);
                    o4[i].z = fmaf(p, vv.z, o4[i].z);
                    o4[i].w = fmaf(p, vv.w, o4[i].w);
                }
            }
        }
    }

    float inv = 1.0f / lrun;
    __half* optr = o + (size_t)(tokBase + qi) * CDIM + h * DH;
    #pragma unroll
    for (int i = 0; i < 12; i++) {
        __half h4[4];
        h4[0] = __float2half_rn(o4[i].x * inv);
        h4[1] = __float2half_rn(o4[i].y * inv);
        h4[2] = __float2half_rn(o4[i].z * inv);
        h4[3] = __float2half_rn(o4[i].w * inv);
        *(uint2*)&optr[i * 4] = *(uint2*)h4;
    }
}

// ---------------- launch ----------------
extern "C" void kernel_launch(void* const* d_in, const int* in_sizes, int n_in,
                              void* d_out, int out_size)
{
    const float* x     = (const float*)d_in[0];
    const float* ln1_g = (const float*)d_in[1];
    const float* ln1_b = (const float*)d_in[2];
    const float* lna_g = (const float*)d_in[3];
    const float* lna_b = (const float*)d_in[4];
    const float* w_qkv = (const float*)d_in[5];
    const float* w_out = (const float*)d_in[6];
    const float* ln2_g = (const float*)d_in[7];
    const float* ln2_b = (const float*)d_in[8];
    const float* w1    = (const float*)d_in[9];
    const float* b1    = (const float*)d_in[10];
    const float* w2    = (const float*)d_in[11];
    const float* b2    = (const float*)d_in[12];
    float* out = (float*)d_out;

    float *t, *qkvb, *t2, *t3;
    __half *ah, *oh, *mh, *hh, *wqkvT, *woutT, *w1T, *w2T;
    cudaGetSymbolAddress((void**)&t,     g_t);
    cudaGetSymbolAddress((void**)&ah,    g_ah);
    cudaGetSymbolAddress((void**)&qkvb,  g_qkv);
    cudaGetSymbolAddress((void**)&oh,    g_oh);
    cudaGetSymbolAddress((void**)&t2,    g_t2);
    cudaGetSymbolAddress((void**)&mh,    g_mh);
    cudaGetSymbolAddress((void**)&hh,    g_hh);
    cudaGetSymbolAddress((void**)&t3,    g_t3);
    cudaGetSymbolAddress((void**)&wqkvT, g_wqkvT);
    cudaGetSymbolAddress((void**)&woutT, g_woutT);
    cudaGetSymbolAddress((void**)&w1T,   g_w1T);
    cudaGetSymbolAddress((void**)&w2T,   g_w2T);

    dim3 tblk(32, 8);
    dim3 tgrid(HW / 32, CDIM / 32, BATCH);

    // weight prep (fp32 [K,N] -> fp16 [N,K])
    wprep_kernel<<<dim3(D3 / 32,  CDIM / 32), tblk>>>(w_qkv, wqkvT, CDIM, D3);
    wprep_kernel<<<dim3(CDIM / 32, CDIM / 32), tblk>>>(w_out, woutT, CDIM, CDIM);
    wprep_kernel<<<dim3(DFF / 32, CDIM / 32), tblk>>>(w1,    w1T,   CDIM, DFF);
    wprep_kernel<<<dim3(CDIM / 32, DFF / 32), tblk>>>(w2,    w2T,   DFF,  CDIM);

    // 1. NCHW -> tokens
    transpose_in_kernel<<<tgrid, tblk>>>(x, t);
    // 2. double pre-norm -> fp16
    ln_kernel<<<NTOK, 128>>>(t, ah, ln1_g, ln1_b, lna_g, lna_b, 1);
    // 3. qkv = a @ w_qkv (fp32 out for attention)
    hgemm_mma<<<dim3(D3 / 128, NTOK / 128), 256>>>(
        ah, wqkvT, qkvb, nullptr, nullptr, nullptr, D3, CDIM, 0);
    // 4. attention -> fp16 o
    attn_kernel<<<dim3(BATCH * HEADS, HW / 128), 128>>>(qkvb, oh);
    // 5. t2 = t + o @ w_out
    hgemm_mma<<<dim3(CDIM / 128, NTOK / 128), 256>>>(
        oh, woutT, t2, nullptr, nullptr, t, CDIM, CDIM, 1);
    // 6. m = LN2(t2) -> fp16
    ln_kernel<<<NTOK, 128>>>(t2, mh, ln2_g, ln2_b, nullptr, nullptr, 0);
    // 7. h = gelu(m @ w1 + b1) -> fp16
    hgemm_mma<<<dim3(DFF / 128, NTOK / 128), 256>>>(
        mh, w1T, nullptr, hh, b1, nullptr, DFF, CDIM, 2);
    // 8. t3 = t2 + h @ w2 + b2
    hgemm_mma<<<dim3(CDIM / 128, NTOK / 128), 256>>>(
        hh, w2T, t3, nullptr, b2, t2, CDIM, DFF, 3);
    // 9. tokens -> NCHW
    transpose_out_kernel<<<tgrid, tblk>>>(t3, out);
}

// round 4
// speedup vs baseline: 6.1025x; 3.1603x over previous
#include <cuda_runtime.h>
#include <cuda_fp16.h>
#include <math.h>
#include <stdint.h>

// ---------------- problem constants ----------------
#define BATCH   8
#define CDIM    384
#define HW      1024
#define NTOK    (BATCH * HW)    // 8192
#define HEADS   8
#define DH      48
#define D3      (3 * CDIM)      // 1152
#define DFF     (4 * CDIM)      // 1536
#define EPSLN   1e-5f

// ---------------- scratch ----------------
__device__ float  g_t  [NTOK * CDIM];
__device__ __half g_ah [NTOK * CDIM];
__device__ __half g_qkvh[NTOK * D3];
__device__ __half g_oh [NTOK * CDIM];
__device__ float  g_t2 [NTOK * CDIM];
__device__ __half g_mh [NTOK * CDIM];
__device__ __half g_hh [NTOK * DFF];
__device__ float  g_t3 [NTOK * CDIM];
__device__ __half g_wqkvT[D3 * CDIM];     // [N,K] fp16
__device__ __half g_woutT[CDIM * CDIM];
__device__ __half g_w1T  [DFF * CDIM];
__device__ __half g_w2T  [CDIM * DFF];

// ---------------- helpers ----------------
__device__ __forceinline__ uint32_t smem_u32(const void* p) {
    uint32_t a;
    asm("{ .reg .u64 t; cvta.to.shared.u64 t, %1; cvt.u32.u64 %0, t; }" : "=r"(a) : "l"(p));
    return a;
}
__device__ __forceinline__ void cp_async16(uint32_t s, const void* g) {
    asm volatile("cp.async.cg.shared.global [%0], [%1], 16;" :: "r"(s), "l"(g));
}
#define CP_COMMIT() asm volatile("cp.async.commit_group;" ::: "memory")
#define CP_WAIT0()  asm volatile("cp.async.wait_group 0;" ::: "memory")
#define CP_WAIT1()  asm volatile("cp.async.wait_group 1;" ::: "memory")

__device__ __forceinline__ void ldmatrix4(uint32_t* r, uint32_t addr) {
    asm volatile("ldmatrix.sync.aligned.m8n8.x4.shared.b16 {%0,%1,%2,%3}, [%4];"
        : "=r"(r[0]), "=r"(r[1]), "=r"(r[2]), "=r"(r[3]) : "r"(addr));
}
__device__ __forceinline__ void ldmatrix4t(uint32_t* r, uint32_t addr) {
    asm volatile("ldmatrix.sync.aligned.m8n8.x4.trans.shared.b16 {%0,%1,%2,%3}, [%4];"
        : "=r"(r[0]), "=r"(r[1]), "=r"(r[2]), "=r"(r[3]) : "r"(addr));
}
__device__ __forceinline__ void mma16816(float* c, const uint32_t* a, const uint32_t* b) {
    asm volatile("mma.sync.aligned.m16n8k16.row.col.f32.f16.f16.f32 "
        "{%0,%1,%2,%3}, {%4,%5,%6,%7}, {%8,%9}, {%0,%1,%2,%3};"
        : "+f"(c[0]), "+f"(c[1]), "+f"(c[2]), "+f"(c[3])
        : "r"(a[0]), "r"(a[1]), "r"(a[2]), "r"(a[3]), "r"(b[0]), "r"(b[1]));
}

// swizzled smem offset for [rows][32 halves] chunk stored as lines of 128B
__device__ __forceinline__ uint32_t swz(uint32_t r, uint32_t g) {
    uint32_t line  = r >> 1;
    uint32_t chunk = (((r & 1u) * 4u + g) ^ (line & 7u));
    return line * 128u + chunk * 16u;
}

// ---------------- transposes ----------------
__global__ void transpose_in_kernel(const float* __restrict__ x, float* __restrict__ t) {
    __shared__ float tile[32][33];
    const int b = blockIdx.z, c0 = blockIdx.y * 32, n0 = blockIdx.x * 32, tx = threadIdx.x;
    #pragma unroll
    for (int i = threadIdx.y; i < 32; i += 8)
        tile[i][tx] = x[(size_t)b * CDIM * HW + (size_t)(c0 + i) * HW + n0 + tx];
    __syncthreads();
    #pragma unroll
    for (int i = threadIdx.y; i < 32; i += 8)
        t[(size_t)(b * HW + n0 + i) * CDIM + c0 + tx] = tile[tx][i];
}

__global__ void transpose_out_kernel(const float* __restrict__ t3, float* __restrict__ out) {
    __shared__ float tile[32][33];
    const int b = blockIdx.z, c0 = blockIdx.y * 32, n0 = blockIdx.x * 32, tx = threadIdx.x;
    #pragma unroll
    for (int i = threadIdx.y; i < 32; i += 8)
        tile[i][tx] = t3[(size_t)(b * HW + n0 + i) * CDIM + c0 + tx];
    __syncthreads();
    #pragma unroll
    for (int i = threadIdx.y; i < 32; i += 8)
        out[(size_t)b * CDIM * HW + (size_t)(c0 + i) * HW + n0 + tx] = tile[tx][i];
}

// weight prep: fp32 [K,N] -> fp16 [N,K]
__global__ void wprep_kernel(const float* __restrict__ w, __half* __restrict__ wt, int K, int N) {
    __shared__ float tile[32][33];
    const int k0 = blockIdx.y * 32, n0 = blockIdx.x * 32, tx = threadIdx.x;
    #pragma unroll
    for (int i = threadIdx.y; i < 32; i += 8)
        tile[i][tx] = w[(size_t)(k0 + i) * N + n0 + tx];
    __syncthreads();
    #pragma unroll
    for (int i = threadIdx.y; i < 32; i += 8)
        wt[(size_t)(n0 + i) * K + k0 + tx] = __float2half_rn(tile[tx][i]);
}

// ---------------- block reduce ----------------
__device__ __forceinline__ float blockSum128(float v) {
    __shared__ float sh[4];
    #pragma unroll
    for (int o = 16; o > 0; o >>= 1) v += __shfl_xor_sync(0xffffffffu, v, o);
    if ((threadIdx.x & 31) == 0) sh[threadIdx.x >> 5] = v;
    __syncthreads();
    float r = sh[0] + sh[1] + sh[2] + sh[3];
    __syncthreads();
    return r;
}

// ---------------- layernorm (fp16 output) ----------------
__global__ __launch_bounds__(128) void ln_kernel(
    const float* __restrict__ in, __half* __restrict__ out,
    const float* __restrict__ g1, const float* __restrict__ b1,
    const float* __restrict__ g2, const float* __restrict__ b2, int dbl)
{
    const int row = blockIdx.x;
    const float* p = in + (size_t)row * CDIM;
    float v[3];
    #pragma unroll
    for (int i = 0; i < 3; i++) v[i] = p[threadIdx.x + i * 128];

    float mu = blockSum128(v[0] + v[1] + v[2]) * (1.0f / CDIM);
    float sq = 0.f;
    #pragma unroll
    for (int i = 0; i < 3; i++) { float d = v[i] - mu; sq += d * d; }
    float rs = rsqrtf(blockSum128(sq) * (1.0f / CDIM) + EPSLN);
    #pragma unroll
    for (int i = 0; i < 3; i++) {
        int c = threadIdx.x + i * 128;
        v[i] = (v[i] - mu) * rs * g1[c] + b1[c];
    }
    if (dbl) {
        float mu2 = blockSum128(v[0] + v[1] + v[2]) * (1.0f / CDIM);
        float sq2 = 0.f;
        #pragma unroll
        for (int i = 0; i < 3; i++) { float d = v[i] - mu2; sq2 += d * d; }
        float rs2 = rsqrtf(blockSum128(sq2) * (1.0f / CDIM) + EPSLN);
        #pragma unroll
        for (int i = 0; i < 3; i++) {
            int c = threadIdx.x + i * 128;
            v[i] = (v[i] - mu2) * rs2 * g2[c] + b2[c];
        }
    }
    #pragma unroll
    for (int i = 0; i < 3; i++)
        out[(size_t)row * CDIM + threadIdx.x + i * 128] = __float2half_rn(v[i]);
}

// ================= HMMA GEMM: 128x128 block, BK=32, 8 warps =================
// epi: 0 -> Cf = acc; 1 -> Cf = acc + res; 2 -> Ch = half(gelu(acc + bias));
//      3 -> Cf = acc + bias + res; 4 -> Ch = half(acc)
__global__ __launch_bounds__(256) void hgemm_mma(
    const __half* __restrict__ A, const __half* __restrict__ B,
    float* __restrict__ Cf, __half* __restrict__ Ch,
    const float* __restrict__ bias, const float* __restrict__ res,
    int N, int K, int epi)
{
    __shared__ __align__(16) __half As[2][128 * 32];
    __shared__ __align__(16) __half Bs[2][128 * 32];

    const int tid = threadIdx.x;
    const int wid = tid >> 5, lid = tid & 31;
    const int row0 = blockIdx.y * 128, col0 = blockIdx.x * 128;
    const int wm = wid & 3;
    const int wn = wid >> 2;

    const uint32_t sA = smem_u32(As);
    const uint32_t sB = smem_u32(Bs);

    const uint32_t rowA = ((lid >> 3) & 1) * 8 + (lid & 7);
    const uint32_t kgA  = (uint32_t)lid >> 4;
    uint32_t aoff[2];
    #pragma unroll
    for (int mt = 0; mt < 2; mt++)
        aoff[mt] = swz(wm * 32 + mt * 16 + rowA, kgA);
    const uint32_t rowB = ((lid >> 4) & 1) * 8 + (lid & 7);
    const uint32_t kgB  = (lid >> 3) & 1;
    uint32_t boff[4];
    #pragma unroll
    for (int nt2 = 0; nt2 < 4; nt2++)
        boff[nt2] = swz(wn * 64 + nt2 * 16 + rowB, kgB);

    float acc[2][8][4];
    #pragma unroll
    for (int i = 0; i < 2; i++)
        #pragma unroll
        for (int j = 0; j < 8; j++)
            #pragma unroll
            for (int q = 0; q < 4; q++) acc[i][j][q] = 0.f;

    const int nc = K >> 5;

    #pragma unroll
    for (int i = 0; i < 2; i++) {
        int v = tid + i * 256;
        int r = v >> 2, g = v & 3;
        uint32_t so = swz(r, g);
        cp_async16(sA + so, A + (size_t)(row0 + r) * K + g * 8);
        cp_async16(sB + so, B + (size_t)(col0 + r) * K + g * 8);
    }
    CP_COMMIT();

    for (int c = 0; c < nc; c++) {
        CP_WAIT0();
        __syncthreads();
        if (c + 1 < nc) {
            const uint32_t bufo = ((c + 1) & 1) * 8192u;
            const int kb = (c + 1) * 32;
            #pragma unroll
            for (int i = 0; i < 2; i++) {
                int v = tid + i * 256;
                int r = v >> 2, g = v & 3;
                uint32_t so = swz(r, g) + bufo;
                cp_async16(sA + so, A + (size_t)(row0 + r) * K + kb + g * 8);
                cp_async16(sB + so, B + (size_t)(col0 + r) * K + kb + g * 8);
            }
            CP_COMMIT();
        }
        const uint32_t bufc = (c & 1) * 8192u;
        #pragma unroll
        for (int kh = 0; kh < 2; kh++) {
            const uint32_t kx = kh * 32u;
            uint32_t a[2][4], b[4][4];
            #pragma unroll
            for (int mt = 0; mt < 2; mt++)
                ldmatrix4(a[mt], sA + bufc + (aoff[mt] ^ kx));
            #pragma unroll
            for (int nt2 = 0; nt2 < 4; nt2++)
                ldmatrix4(b[nt2], sB + bufc + (boff[nt2] ^ kx));
            #pragma unroll
            for (int mt = 0; mt < 2; mt++)
                #pragma unroll
                for (int nt = 0; nt < 8; nt++)
                    mma16816(acc[mt][nt], a[mt], &b[nt >> 1][(nt & 1) * 2]);
        }
    }

    const int gid = lid >> 2, tig = lid & 3;
    #pragma unroll
    for (int mt = 0; mt < 2; mt++) {
        #pragma unroll
        for (int nt = 0; nt < 8; nt++) {
            const int cc = col0 + wn * 64 + nt * 8 + tig * 2;
            #pragma unroll
            for (int half = 0; half < 2; half++) {
                const int r = row0 + wm * 32 + mt * 16 + gid + half * 8;
                float v0 = acc[mt][nt][half * 2 + 0];
                float v1 = acc[mt][nt][half * 2 + 1];
                if (epi == 1) {
                    v0 += res[(size_t)r * N + cc];
                    v1 += res[(size_t)r * N + cc + 1];
                } else if (epi == 2) {
                    v0 += bias[cc];     v1 += bias[cc + 1];
                    v0 = 0.5f * v0 * (1.0f + erff(v0 * 0.70710678118654752f));
                    v1 = 0.5f * v1 * (1.0f + erff(v1 * 0.70710678118654752f));
                } else if (epi == 3) {
                    v0 += bias[cc] + res[(size_t)r * N + cc];
                    v1 += bias[cc + 1] + res[(size_t)r * N + cc + 1];
                }
                if (epi == 2 || epi == 4) {
                    __half2 h2 = __floats2half2_rn(v0, v1);
                    *(__half2*)&Ch[(size_t)r * N + cc] = h2;
                } else {
                    float2 f2 = make_float2(v0, v1);
                    *(float2*)&Cf[(size_t)r * N + cc] = f2;
                }
            }
        }
    }
}

// ================= flash attention via HMMA =================
// grid (64 bh, 8 qblocks), 256 threads (8 warps x 16 query rows)
__device__ __forceinline__ void load_kv_tile(
    const __half* base, int t, int buf, uint32_t sKa, uint32_t sVa, int tid)
{
    const __half* ksrc = base + CDIM;
    const __half* vsrc = base + 2 * CDIM;
    #pragma unroll
    for (int i = tid; i < 768; i += 256) {
        if (i < 384) {
            int r = i / 6, j = i % 6;
            int ch = j >> 2, g = j & 3;
            cp_async16(sKa + buf * 8192u + ch * 4096u + swz(r, g),
                       ksrc + (size_t)(t * 64 + r) * D3 + j * 8);
        } else {
            int v = i - 384;
            int r = v / 6, j = v % 6;
            cp_async16(sVa + buf * 7168u + r * 112u + j * 16u,
                       vsrc + (size_t)(t * 64 + r) * D3 + j * 8);
        }
    }
}

__global__ __launch_bounds__(256) void attn_mma(
    const __half* __restrict__ qkv, __half* __restrict__ o)
{
    __shared__ __align__(16) __half sQ[2][128 * 32];     // 16 KB
    __shared__ __align__(16) __half sK[2][2][64 * 32];   // 16 KB
    __shared__ __align__(16) __half sV[2][64 * 56];      // 14 KB

    const int bh = blockIdx.x;
    const int b = bh >> 3, h = bh & 7;
    const int q0 = blockIdx.y * 128;
    const int tid = threadIdx.x, wid = tid >> 5, lid = tid & 31;
    const __half* base = qkv + (size_t)(b * HW) * D3 + h * DH;

    const uint32_t sQa = smem_u32(sQ);
    const uint32_t sKa = smem_u32(sK);
    const uint32_t sVa = smem_u32(sV);

    // load Q tile (128 x 48 into 2 swizzled chunks)
    for (int i = tid; i < 768; i += 256) {
        int r = i / 6, j = i % 6;
        int ch = j >> 2, g = j & 3;
        cp_async16(sQa + ch * 8192u + swz(r, g), base + (size_t)(q0 + r) * D3 + j * 8);
    }
    load_kv_tile(base, 0, 0, sKa, sVa, tid);
    CP_COMMIT();

    // fragment offsets
    const uint32_t rowA = ((lid >> 3) & 1) * 8 + (lid & 7);
    const uint32_t kgA  = (uint32_t)lid >> 4;
    const uint32_t aoff = swz(wid * 16 + rowA, kgA);
    const uint32_t rowB = ((lid >> 4) & 1) * 8 + (lid & 7);
    const uint32_t kgB  = (lid >> 3) & 1;
    uint32_t boff[4];
    #pragma unroll
    for (int nt2 = 0; nt2 < 4; nt2++)
        boff[nt2] = swz(nt2 * 16 + rowB, kgB);
    // V trans-ldmatrix per-lane byte offset (within buffer)
    const uint32_t voff = (uint32_t)(lid & 15) * 112u + ((lid >> 4) & 1) * 16u;

    const float SCL2 = 0.14433756729740645f * 1.4426950408889634f;

    uint32_t aq[3][4];
    float oa[6][4];
    #pragma unroll
    for (int i = 0; i < 6; i++)
        #pragma unroll
        for (int q = 0; q < 4; q++) oa[i][q] = 0.f;
    float m0 = -1e30f, m1 = -1e30f, l0 = 0.f, l1 = 0.f;

    for (int t = 0; t < 16; t++) {
        const int buf = t & 1;
        if (t + 1 < 16) {
            load_kv_tile(base, t + 1, buf ^ 1, sKa, sVa, tid);
            CP_COMMIT();
            CP_WAIT1();
        } else {
            CP_WAIT0();
        }
        __syncthreads();

        if (t == 0) {
            ldmatrix4(aq[0], sQa + aoff);
            ldmatrix4(aq[1], sQa + (aoff ^ 32u));
            ldmatrix4(aq[2], sQa + 8192u + aoff);
        }

        // S = Q K^T  (dh = 48 -> 3 k-steps)
        float c[8][4];
        #pragma unroll
        for (int nt = 0; nt < 8; nt++)
            #pragma unroll
            for (int q = 0; q < 4; q++) c[nt][q] = 0.f;
        #pragma unroll
        for (int ks = 0; ks < 3; ks++) {
            const uint32_t kbase = sKa + buf * 8192u + (ks >> 1) * 4096u;
            const uint32_t kx = (ks & 1) * 32u;
            uint32_t bf[4][4];
            #pragma unroll
            for (int nt2 = 0; nt2 < 4; nt2++)
                ldmatrix4(bf[nt2], kbase + (boff[nt2] ^ kx));
            #pragma unroll
            for (int nt = 0; nt < 8; nt++)
                mma16816(c[nt], aq[ks], &bf[nt >> 1][(nt & 1) * 2]);
        }

        // online softmax (scaled to log2 domain)
        float mx0 = -1e30f, mx1 = -1e30f;
        #pragma unroll
        for (int nt = 0; nt < 8; nt++) {
            mx0 = fmaxf(mx0, fmaxf(c[nt][0], c[nt][1]));
            mx1 = fmaxf(mx1, fmaxf(c[nt][2], c[nt][3]));
        }
        mx0 = fmaxf(mx0, __shfl_xor_sync(0xffffffffu, mx0, 1));
        mx0 = fmaxf(mx0, __shfl_xor_sync(0xffffffffu, mx0, 2));
        mx1 = fmaxf(mx1, __shfl_xor_sync(0xffffffffu, mx1, 1));
        mx1 = fmaxf(mx1, __shfl_xor_sync(0xffffffffu, mx1, 2));
        mx0 *= SCL2; mx1 *= SCL2;
        const float nm0 = fmaxf(m0, mx0), nm1 = fmaxf(m1, mx1);
        const float cr0 = exp2f(m0 - nm0), cr1 = exp2f(m1 - nm1);
        m0 = nm0; m1 = nm1;

        float s0 = 0.f, s1 = 0.f;
        uint32_t pf[8][2];
        #pragma unroll
        for (int nt = 0; nt < 8; nt++) {
            float p0 = exp2f(c[nt][0] * SCL2 - nm0);
            float p1 = exp2f(c[nt][1] * SCL2 - nm0);
            float p2 = exp2f(c[nt][2] * SCL2 - nm1);
            float p3 = exp2f(c[nt][3] * SCL2 - nm1);
            s0 += p0 + p1; s1 += p2 + p3;
            __half2 h01 = __floats2half2_rn(p0, p1);
            __half2 h23 = __floats2half2_rn(p2, p3);
            pf[nt][0] = *(uint32_t*)&h01;
            pf[nt][1] = *(uint32_t*)&h23;
        }
        s0 += __shfl_xor_sync(0xffffffffu, s0, 1);
        s0 += __shfl_xor_sync(0xffffffffu, s0, 2);
        s1 += __shfl_xor_sync(0xffffffffu, s1, 1);
        s1 += __shfl_xor_sync(0xffffffffu, s1, 2);
        l0 = l0 * cr0 + s0;
        l1 = l1 * cr1 + s1;

        // rescale O
        #pragma unroll
        for (int nt = 0; nt < 6; nt++) {
            oa[nt][0] *= cr0; oa[nt][1] *= cr0;
            oa[nt][2] *= cr1; oa[nt][3] *= cr1;
        }

        // O += P V  (4 k-steps over 64 tokens, 6 n-tiles over dh 48)
        const uint32_t vb0 = sVa + buf * 7168u + voff;
        #pragma unroll
        for (int kt = 0; kt < 4; kt++) {
            uint32_t pa[4] = { pf[2 * kt][0], pf[2 * kt][1],
                               pf[2 * kt + 1][0], pf[2 * kt + 1][1] };
            uint32_t vb[3][4];
            #pragma unroll
            for (int q = 0; q < 3; q++)
                ldmatrix4t(vb[q], vb0 + kt * 16u * 112u + q * 32u);
            #pragma unroll
            for (int nt = 0; nt < 6; nt++)
                mma16816(oa[nt], pa, &vb[nt >> 1][(nt & 1) * 2]);
        }
        __syncthreads();
    }

    // epilogue
    const float inv0 = 1.0f / l0, inv1 = 1.0f / l1;
    const int gid = lid >> 2, tig = lid & 3;
    const int r0 = q0 + wid * 16 + gid;
    __half* op = o + (size_t)(b * HW) * CDIM + h * DH;
    #pragma unroll
    for (int nt = 0; nt < 6; nt++) {
        const int col = nt * 8 + tig * 2;
        __half2 h0 = __floats2half2_rn(oa[nt][0] * inv0, oa[nt][1] * inv0);
        __half2 h1 = __floats2half2_rn(oa[nt][2] * inv1, oa[nt][3] * inv1);
        *(__half2*)&op[(size_t)r0 * CDIM + col] = h0;
        *(__half2*)&op[(size_t)(r0 + 8) * CDIM + col] = h1;
    }
}

// ---------------- launch ----------------
extern "C" void kernel_launch(void* const* d_in, const int* in_sizes, int n_in,
                              void* d_out, int out_size)
{
    const float* x     = (const float*)d_in[0];
    const float* ln1_g = (const float*)d_in[1];
    const float* ln1_b = (const float*)d_in[2];
    const float* lna_g = (const float*)d_in[3];
    const float* lna_b = (const float*)d_in[4];
    const float* w_qkv = (const float*)d_in[5];
    const float* w_out = (const float*)d_in[6];
    const float* ln2_g = (const float*)d_in[7];
    const float* ln2_b = (const float*)d_in[8];
    const float* w1    = (const float*)d_in[9];
    const float* b1    = (const float*)d_in[10];
    const float* w2    = (const float*)d_in[11];
    const float* b2    = (const float*)d_in[12];
    float* out = (float*)d_out;

    float *t, *t2, *t3;
    __half *ah, *qkvh, *oh, *mh, *hh, *wqkvT, *woutT, *w1T, *w2T;
    cudaGetSymbolAddress((void**)&t,     g_t);
    cudaGetSymbolAddress((void**)&ah,    g_ah);
    cudaGetSymbolAddress((void**)&qkvh,  g_qkvh);
    cudaGetSymbolAddress((void**)&oh,    g_oh);
    cudaGetSymbolAddress((void**)&t2,    g_t2);
    cudaGetSymbolAddress((void**)&mh,    g_mh);
    cudaGetSymbolAddress((void**)&hh,    g_hh);
    cudaGetSymbolAddress((void**)&t3,    g_t3);
    cudaGetSymbolAddress((void**)&wqkvT, g_wqkvT);
    cudaGetSymbolAddress((void**)&woutT, g_woutT);
    cudaGetSymbolAddress((void**)&w1T,   g_w1T);
    cudaGetSymbolAddress((void**)&w2T,   g_w2T);

    dim3 tblk(32, 8);
    dim3 tgrid(HW / 32, CDIM / 32, BATCH);

    wprep_kernel<<<dim3(D3 / 32,  CDIM / 32), tblk>>>(w_qkv, wqkvT, CDIM, D3);
    wprep_kernel<<<dim3(CDIM / 32, CDIM / 32), tblk>>>(w_out, woutT, CDIM, CDIM);
    wprep_kernel<<<dim3(DFF / 32, CDIM / 32), tblk>>>(w1,    w1T,   CDIM, DFF);
    wprep_kernel<<<dim3(CDIM / 32, DFF / 32), tblk>>>(w2,    w2T,   DFF,  CDIM);

    transpose_in_kernel<<<tgrid, tblk>>>(x, t);
    ln_kernel<<<NTOK, 128>>>(t, ah, ln1_g, ln1_b, lna_g, lna_b, 1);
    // qkv = a @ w_qkv (fp16 out)
    hgemm_mma<<<dim3(D3 / 128, NTOK / 128), 256>>>(
        ah, wqkvT, nullptr, qkvh, nullptr, nullptr, D3, CDIM, 4);
    // flash attention
    attn_mma<<<dim3(BATCH * HEADS, HW / 128), 256>>>(qkvh, oh);
    // t2 = t + o @ w_out
    hgemm_mma<<<dim3(CDIM / 128, NTOK / 128), 256>>>(
        oh, woutT, t2, nullptr, nullptr, t, CDIM, CDIM, 1);
    ln_kernel<<<NTOK, 128>>>(t2, mh, ln2_g, ln2_b, nullptr, nullptr, 0);
    // h = gelu(m @ w1 + b1)
    hgemm_mma<<<dim3(DFF / 128, NTOK / 128), 256>>>(
        mh, w1T, nullptr, hh, b1, nullptr, DFF, CDIM, 2);
    // t3 = t2 + h @ w2 + b2
    hgemm_mma<<<dim3(CDIM / 128, NTOK / 128), 256>>>(
        hh, w2T, t3, nullptr, b2, t2, CDIM, DFF, 3);
    transpose_out_kernel<<<tgrid, tblk>>>(t3, out);
}

// round 5
// speedup vs baseline: 6.2378x; 1.0222x over previous
#include <cuda_runtime.h>
#include <cuda_fp16.h>
#include <math.h>
#include <stdint.h>

// ---------------- problem constants ----------------
#define BATCH   8
#define CDIM    384
#define HW      1024
#define NTOK    (BATCH * HW)    // 8192
#define HEADS   8
#define DH      48
#define D3      (3 * CDIM)      // 1152
#define DFF     (4 * CDIM)      // 1536
#define EPSLN   1e-5f

// ---------------- scratch ----------------
__device__ float  g_t  [NTOK * CDIM];
__device__ __half g_ah [NTOK * CDIM];
__device__ __half g_qkvh[NTOK * D3];
__device__ __half g_oh [NTOK * CDIM];
__device__ float  g_t2 [NTOK * CDIM];
__device__ __half g_mh [NTOK * CDIM];
__device__ __half g_hh [NTOK * DFF];
__device__ float  g_t3 [NTOK * CDIM];
__device__ __half g_wqkvT[D3 * CDIM];     // [N,K] fp16
__device__ __half g_woutT[CDIM * CDIM];
__device__ __half g_w1T  [DFF * CDIM];
__device__ __half g_w2T  [CDIM * DFF];

// ---------------- helpers ----------------
__device__ __forceinline__ uint32_t smem_u32(const void* p) {
    uint32_t a;
    asm("{ .reg .u64 t; cvta.to.shared.u64 t, %1; cvt.u32.u64 %0, t; }" : "=r"(a) : "l"(p));
    return a;
}
__device__ __forceinline__ void cp_async16(uint32_t s, const void* g) {
    asm volatile("cp.async.cg.shared.global [%0], [%1], 16;" :: "r"(s), "l"(g));
}
#define CP_COMMIT() asm volatile("cp.async.commit_group;" ::: "memory")
#define CP_WAIT0()  asm volatile("cp.async.wait_group 0;" ::: "memory")
#define CP_WAIT1()  asm volatile("cp.async.wait_group 1;" ::: "memory")

__device__ __forceinline__ void ldmatrix4(uint32_t* r, uint32_t addr) {
    asm volatile("ldmatrix.sync.aligned.m8n8.x4.shared.b16 {%0,%1,%2,%3}, [%4];"
        : "=r"(r[0]), "=r"(r[1]), "=r"(r[2]), "=r"(r[3]) : "r"(addr));
}
__device__ __forceinline__ void ldmatrix4t(uint32_t* r, uint32_t addr) {
    asm volatile("ldmatrix.sync.aligned.m8n8.x4.trans.shared.b16 {%0,%1,%2,%3}, [%4];"
        : "=r"(r[0]), "=r"(r[1]), "=r"(r[2]), "=r"(r[3]) : "r"(addr));
}
__device__ __forceinline__ void mma16816(float* c, const uint32_t* a, const uint32_t* b) {
    asm volatile("mma.sync.aligned.m16n8k16.row.col.f32.f16.f16.f32 "
        "{%0,%1,%2,%3}, {%4,%5,%6,%7}, {%8,%9}, {%0,%1,%2,%3};"
        : "+f"(c[0]), "+f"(c[1]), "+f"(c[2]), "+f"(c[3])
        : "r"(a[0]), "r"(a[1]), "r"(a[2]), "r"(a[3]), "r"(b[0]), "r"(b[1]));
}

// swizzled smem offset for [rows][32 halves] chunk stored as lines of 128B
__device__ __forceinline__ uint32_t swz(uint32_t r, uint32_t g) {
    uint32_t line  = r >> 1;
    uint32_t chunk = (((r & 1u) * 4u + g) ^ (line & 7u));
    return line * 128u + chunk * 16u;
}

// ---------------- fused input transpose + double layernorm ----------------
// block: 32 tokens of one batch; x NCHW read coalesced; writes t (fp32) + ah (fp16)
#define LNSMEM (CDIM * 33 * 4)
__global__ __launch_bounds__(256) void prep_ln_kernel(
    const float* __restrict__ x, float* __restrict__ t, __half* __restrict__ ah,
    const float* __restrict__ g1, const float* __restrict__ b1,
    const float* __restrict__ g2, const float* __restrict__ b2)
{
    extern __shared__ float sv[];            // [CDIM][33]
    __shared__ float red[2][8][32];
    __shared__ float smu[32], srs[32], smu2[32], srs2[32];
    const int b = blockIdx.y, n0 = blockIdx.x * 32;
    const int tid = threadIdx.x, lane = tid & 31, cg = tid >> 5;

    float sum = 0.f, ss = 0.f;
    for (int c = cg; c < CDIM; c += 8) {
        float v = x[(size_t)b * CDIM * HW + (size_t)c * HW + n0 + lane];
        sv[c * 33 + lane] = v;
        sum += v; ss += v * v;
    }
    red[0][cg][lane] = sum; red[1][cg][lane] = ss;
    __syncthreads();
    if (tid < 32) {
        float s = 0.f, q = 0.f;
        #pragma unroll
        for (int g = 0; g < 8; g++) { s += red[0][g][tid]; q += red[1][g][tid]; }
        float mu = s * (1.0f / CDIM);
        smu[tid] = mu;
        srs[tid] = rsqrtf(q * (1.0f / CDIM) - mu * mu + EPSLN);
    }
    __syncthreads();
    {
        const float mu = smu[lane], rs = srs[lane];
        sum = 0.f; ss = 0.f;
        for (int c = cg; c < CDIM; c += 8) {
            float y = (sv[c * 33 + lane] - mu) * rs * g1[c] + b1[c];
            sum += y; ss += y * y;
        }
    }
    red[0][cg][lane] = sum; red[1][cg][lane] = ss;
    __syncthreads();
    if (tid < 32) {
        float s = 0.f, q = 0.f;
        #pragma unroll
        for (int g = 0; g < 8; g++) { s += red[0][g][tid]; q += red[1][g][tid]; }
        float mu = s * (1.0f / CDIM);
        smu2[tid] = mu;
        srs2[tid] = rsqrtf(q * (1.0f / CDIM) - mu * mu + EPSLN);
    }
    __syncthreads();
    for (int w = tid; w < CDIM * 32; w += 256) {
        int token = w / CDIM, c = w - token * CDIM;
        float v = sv[c * 33 + token];
        float y = (v - smu[token]) * srs[token] * g1[c] + b1[c];
        float z = (y - smu2[token]) * srs2[token] * g2[c] + b2[c];
        size_t idx = ((size_t)(b * HW + n0 + token)) * CDIM + c;
        t[idx] = v;
        ah[idx] = __float2half_rn(z);
    }
}

// ---------------- output transpose ----------------
__global__ void transpose_out_kernel(const float* __restrict__ t3, float* __restrict__ out) {
    __shared__ float tile[32][33];
    const int b = blockIdx.z, c0 = blockIdx.y * 32, n0 = blockIdx.x * 32, tx = threadIdx.x;
    #pragma unroll
    for (int i = threadIdx.y; i < 32; i += 8)
        tile[i][tx] = t3[(size_t)(b * HW + n0 + i) * CDIM + c0 + tx];
    __syncthreads();
    #pragma unroll
    for (int i = threadIdx.y; i < 32; i += 8)
        out[(size_t)b * CDIM * HW + (size_t)(c0 + i) * HW + n0 + tx] = tile[tx][i];
}

// ---------------- merged weight prep (fp32 [K,N] -> fp16 [N,K], all 4 weights) ----
__global__ void wprep_all_kernel(
    const float* __restrict__ wq, const float* __restrict__ wo,
    const float* __restrict__ w1, const float* __restrict__ w2,
    __half* __restrict__ wqT, __half* __restrict__ woT,
    __half* __restrict__ w1T, __half* __restrict__ w2T)
{
    __shared__ float tile[32][33];
    const int bid = blockIdx.x;
    const float* w; __half* wt; int K, N, nb, loc;
    if (bid < 432)       { w = wq; wt = wqT; K = CDIM; N = D3;   loc = bid;        nb = 36; }
    else if (bid < 576)  { w = wo; wt = woT; K = CDIM; N = CDIM; loc = bid - 432;  nb = 12; }
    else if (bid < 1152) { w = w1; wt = w1T; K = CDIM; N = DFF;  loc = bid - 576;  nb = 48; }
    else                 { w = w2; wt = w2T; K = DFF;  N = CDIM; loc = bid - 1152; nb = 12; }
    const int n0 = (loc % nb) * 32, k0 = (loc / nb) * 32, tx = threadIdx.x;
    #pragma unroll
    for (int i = threadIdx.y; i < 32; i += 8)
        tile[i][tx] = w[(size_t)(k0 + i) * N + n0 + tx];
    __syncthreads();
    #pragma unroll
    for (int i = threadIdx.y; i < 32; i += 8)
        wt[(size_t)(n0 + i) * K + k0 + tx] = __float2half_rn(tile[tx][i]);
}

// ---------------- block reduce (LN2) ----------------
__device__ __forceinline__ float blockSum128(float v) {
    __shared__ float sh[4];
    #pragma unroll
    for (int o = 16; o > 0; o >>= 1) v += __shfl_xor_sync(0xffffffffu, v, o);
    if ((threadIdx.x & 31) == 0) sh[threadIdx.x >> 5] = v;
    __syncthreads();
    float r = sh[0] + sh[1] + sh[2] + sh[3];
    __syncthreads();
    return r;
}

__global__ __launch_bounds__(128) void ln_kernel(
    const float* __restrict__ in, __half* __restrict__ out,
    const float* __restrict__ g1, const float* __restrict__ b1)
{
    const int row = blockIdx.x;
    const float* p = in + (size_t)row * CDIM;
    float v[3];
    #pragma unroll
    for (int i = 0; i < 3; i++) v[i] = p[threadIdx.x + i * 128];
    float mu = blockSum128(v[0] + v[1] + v[2]) * (1.0f / CDIM);
    float sq = 0.f;
    #pragma unroll
    for (int i = 0; i < 3; i++) { float d = v[i] - mu; sq += d * d; }
    float rs = rsqrtf(blockSum128(sq) * (1.0f / CDIM) + EPSLN);
    #pragma unroll
    for (int i = 0; i < 3; i++) {
        int c = threadIdx.x + i * 128;
        out[(size_t)row * CDIM + c] = __float2half_rn((v[i] - mu) * rs * g1[c] + b1[c]);
    }
}

// ================= HMMA GEMM: 128x128 block, BK=32, 3-stage pipeline ==========
// epi: 0 -> Cf = acc; 1 -> Cf = acc + res; 2 -> Ch = half(gelu(acc + bias));
//      3 -> Cf = acc + bias + res; 4 -> Ch = half(acc)
__global__ __launch_bounds__(256) void hgemm_mma(
    const __half* __restrict__ A, const __half* __restrict__ B,
    float* __restrict__ Cf, __half* __restrict__ Ch,
    const float* __restrict__ bias, const float* __restrict__ res,
    int N, int K, int epi)
{
    __shared__ __align__(16) __half As[3][128 * 32];
    __shared__ __align__(16) __half Bs[3][128 * 32];

    const int tid = threadIdx.x;
    const int wid = tid >> 5, lid = tid & 31;
    const int row0 = blockIdx.y * 128, col0 = blockIdx.x * 128;
    const int wm = wid & 3;
    const int wn = wid >> 2;

    const uint32_t sA = smem_u32(As);
    const uint32_t sB = smem_u32(Bs);

    const uint32_t rowA = ((lid >> 3) & 1) * 8 + (lid & 7);
    const uint32_t kgA  = (uint32_t)lid >> 4;
    uint32_t aoff[2];
    #pragma unroll
    for (int mt = 0; mt < 2; mt++)
        aoff[mt] = swz(wm * 32 + mt * 16 + rowA, kgA);
    const uint32_t rowB = ((lid >> 4) & 1) * 8 + (lid & 7);
    const uint32_t kgB  = (lid >> 3) & 1;
    uint32_t boff[4];
    #pragma unroll
    for (int nt2 = 0; nt2 < 4; nt2++)
        boff[nt2] = swz(wn * 64 + nt2 * 16 + rowB, kgB);

    float acc[2][8][4];
    #pragma unroll
    for (int i = 0; i < 2; i++)
        #pragma unroll
        for (int j = 0; j < 8; j++)
            #pragma unroll
            for (int q = 0; q < 4; q++) acc[i][j][q] = 0.f;

    const int nc = K >> 5;
    const int ldr = tid >> 2, ldg = tid & 3;

    auto LOADC = [&](int cc, int bi) {
        const uint32_t bufo = (uint32_t)bi * 8192u;
        const int kb = cc * 32;
        #pragma unroll
        for (int i = 0; i < 2; i++) {
            int r = ldr + i * 64;
            uint32_t so = swz(r, ldg) + bufo;
            cp_async16(sA + so, A + (size_t)(row0 + r) * K + kb + ldg * 8);
            cp_async16(sB + so, B + (size_t)(col0 + r) * K + kb + ldg * 8);
        }
    };

    LOADC(0, 0); CP_COMMIT();
    LOADC(1, 1); CP_COMMIT();

    int bufc = 0;
    for (int c = 0; c < nc; c++) {
        if (c == nc - 1) { CP_WAIT0(); } else { CP_WAIT1(); }
        __syncthreads();
        if (c + 2 < nc) {
            int bi = bufc + 2; if (bi >= 3) bi -= 3;
            LOADC(c + 2, bi);
            CP_COMMIT();
        }
        const uint32_t bo = (uint32_t)bufc * 8192u;
        #pragma unroll
        for (int kh = 0; kh < 2; kh++) {
            const uint32_t kx = kh * 32u;
            uint32_t a[2][4], b[4][4];
            #pragma unroll
            for (int mt = 0; mt < 2; mt++)
                ldmatrix4(a[mt], sA + bo + (aoff[mt] ^ kx));
            #pragma unroll
            for (int nt2 = 0; nt2 < 4; nt2++)
                ldmatrix4(b[nt2], sB + bo + (boff[nt2] ^ kx));
            #pragma unroll
            for (int mt = 0; mt < 2; mt++)
                #pragma unroll
                for (int nt = 0; nt < 8; nt++)
                    mma16816(acc[mt][nt], a[mt], &b[nt >> 1][(nt & 1) * 2]);
        }
        if (++bufc >= 3) bufc = 0;
    }

    const int gid = lid >> 2, tig = lid & 3;
    #pragma unroll
    for (int mt = 0; mt < 2; mt++) {
        #pragma unroll
        for (int nt = 0; nt < 8; nt++) {
            const int cc = col0 + wn * 64 + nt * 8 + tig * 2;
            #pragma unroll
            for (int half = 0; half < 2; half++) {
                const int r = row0 + wm * 32 + mt * 16 + gid + half * 8;
                float v0 = acc[mt][nt][half * 2 + 0];
                float v1 = acc[mt][nt][half * 2 + 1];
                if (epi == 1) {
                    v0 += res[(size_t)r * N + cc];
                    v1 += res[(size_t)r * N + cc + 1];
                } else if (epi == 2) {
                    v0 += bias[cc];     v1 += bias[cc + 1];
                    v0 = 0.5f * v0 * (1.0f + erff(v0 * 0.70710678118654752f));
                    v1 = 0.5f * v1 * (1.0f + erff(v1 * 0.70710678118654752f));
                } else if (epi == 3) {
                    v0 += bias[cc] + res[(size_t)r * N + cc];
                    v1 += bias[cc + 1] + res[(size_t)r * N + cc + 1];
                }
                if (epi == 2 || epi == 4) {
                    __half2 h2 = __floats2half2_rn(v0, v1);
                    *(__half2*)&Ch[(size_t)r * N + cc] = h2;
                } else {
                    float2 f2 = make_float2(v0, v1);
                    *(float2*)&Cf[(size_t)r * N + cc] = f2;
                }
            }
        }
    }
}

// ================= flash attention via HMMA (3-stage KV pipeline) =============
// dyn smem: sQ 16384 | sK 3*8192=24576 | sV 3*7168=21504  => 62464
#define ATT_SMEM (16384 + 24576 + 21504)

__device__ __forceinline__ void load_kv_tile(
    const __half* base, int t, int buf, uint32_t sKa, uint32_t sVa, int tid)
{
    const __half* ksrc = base + CDIM;
    const __half* vsrc = base + 2 * CDIM;
    #pragma unroll
    for (int i = tid; i < 768; i += 256) {
        if (i < 384) {
            int r = i / 6, j = i % 6;
            int ch = j >> 2, g = j & 3;
            cp_async16(sKa + (uint32_t)buf * 8192u + ch * 4096u + swz(r, g),
                       ksrc + (size_t)(t * 64 + r) * D3 + j * 8);
        } else {
            int v = i - 384;
            int r = v / 6, j = v % 6;
            cp_async16(sVa + (uint32_t)buf * 7168u + r * 112u + j * 16u,
                       vsrc + (size_t)(t * 64 + r) * D3 + j * 8);
        }
    }
}

__global__ __launch_bounds__(256) void attn_mma(
    const __half* __restrict__ qkv, __half* __restrict__ o)
{
    extern __shared__ __align__(16) char asmem[];
    const uint32_t sQa = smem_u32(asmem);
    const uint32_t sKa = sQa + 16384u;
    const uint32_t sVa = sKa + 24576u;

    const int bh = blockIdx.x;
    const int b = bh >> 3, h = bh & 7;
    const int q0 = blockIdx.y * 128;
    const int tid = threadIdx.x, wid = tid >> 5, lid = tid & 31;
    const __half* base = qkv + (size_t)(b * HW) * D3 + h * DH;

    // group 0: Q tile + KV tile 0 ; group 1: KV tile 1
    for (int i = tid; i < 768; i += 256) {
        int r = i / 6, j = i % 6;
        int ch = j >> 2, g = j & 3;
        cp_async16(sQa + ch * 8192u + swz(r, g), base + (size_t)(q0 + r) * D3 + j * 8);
    }
    load_kv_tile(base, 0, 0, sKa, sVa, tid);
    CP_COMMIT();
    load_kv_tile(base, 1, 1, sKa, sVa, tid);
    CP_COMMIT();

    const uint32_t rowA = ((lid >> 3) & 1) * 8 + (lid & 7);
    const uint32_t kgA  = (uint32_t)lid >> 4;
    const uint32_t aoff = swz(wid * 16 + rowA, kgA);
    const uint32_t rowB = ((lid >> 4) & 1) * 8 + (lid & 7);
    const uint32_t kgB  = (lid >> 3) & 1;
    uint32_t boff[4];
    #pragma unroll
    for (int nt2 = 0; nt2 < 4; nt2++)
        boff[nt2] = swz(nt2 * 16 + rowB, kgB);
    const uint32_t voff = (uint32_t)(lid & 15) * 112u + ((lid >> 4) & 1) * 16u;

    const float SCL2 = 0.14433756729740645f * 1.4426950408889634f;

    uint32_t aq[3][4];
    float oa[6][4];
    #pragma unroll
    for (int i = 0; i < 6; i++)
        #pragma unroll
        for (int q = 0; q < 4; q++) oa[i][q] = 0.f;
    float m0 = -1e30f, m1 = -1e30f, l0 = 0.f, l1 = 0.f;

    int buf = 0;
    for (int t = 0; t < 16; t++) {
        if (t == 15) { CP_WAIT0(); } else { CP_WAIT1(); }
        __syncthreads();
        if (t + 2 < 16) {
            int bi = buf + 2; if (bi >= 3) bi -= 3;
            load_kv_tile(base, t + 2, bi, sKa, sVa, tid);
            CP_COMMIT();
        }

        if (t == 0) {
            ldmatrix4(aq[0], sQa + aoff);
            ldmatrix4(aq[1], sQa + (aoff ^ 32u));
            ldmatrix4(aq[2], sQa + 8192u + aoff);
        }

        // S = Q K^T
        float c[8][4];
        #pragma unroll
        for (int nt = 0; nt < 8; nt++)
            #pragma unroll
            for (int q = 0; q < 4; q++) c[nt][q] = 0.f;
        #pragma unroll
        for (int ks = 0; ks < 3; ks++) {
            const uint32_t kbase = sKa + (uint32_t)buf * 8192u + (ks >> 1) * 4096u;
            const uint32_t kx = (ks & 1) * 32u;
            uint32_t bf[4][4];
            #pragma unroll
            for (int nt2 = 0; nt2 < 4; nt2++)
                ldmatrix4(bf[nt2], kbase + (boff[nt2] ^ kx));
            #pragma unroll
            for (int nt = 0; nt < 8; nt++)
                mma16816(c[nt], aq[ks], &bf[nt >> 1][(nt & 1) * 2]);
        }

        // online softmax (log2 domain)
        float mx0 = -1e30f, mx1 = -1e30f;
        #pragma unroll
        for (int nt = 0; nt < 8; nt++) {
            mx0 = fmaxf(mx0, fmaxf(c[nt][0], c[nt][1]));
            mx1 = fmaxf(mx1, fmaxf(c[nt][2], c[nt][3]));
        }
        mx0 = fmaxf(mx0, __shfl_xor_sync(0xffffffffu, mx0, 1));
        mx0 = fmaxf(mx0, __shfl_xor_sync(0xffffffffu, mx0, 2));
        mx1 = fmaxf(mx1, __shfl_xor_sync(0xffffffffu, mx1, 1));
        mx1 = fmaxf(mx1, __shfl_xor_sync(0xffffffffu, mx1, 2));
        mx0 *= SCL2; mx1 *= SCL2;
        const float nm0 = fmaxf(m0, mx0), nm1 = fmaxf(m1, mx1);
        const float cr0 = exp2f(m0 - nm0), cr1 = exp2f(m1 - nm1);
        m0 = nm0; m1 = nm1;

        float s0 = 0.f, s1 = 0.f;
        uint32_t pf[8][2];
        #pragma unroll
        for (int nt = 0; nt < 8; nt++) {
            float p0 = exp2f(c[nt][0] * SCL2 - nm0);
            float p1 = exp2f(c[nt][1] * SCL2 - nm0);
            float p2 = exp2f(c[nt][2] * SCL2 - nm1);
            float p3 = exp2f(c[nt][3] * SCL2 - nm1);
            s0 += p0 + p1; s1 += p2 + p3;
            __half2 h01 = __floats2half2_rn(p0, p1);
            __half2 h23 = __floats2half2_rn(p2, p3);
            pf[nt][0] = *(uint32_t*)&h01;
            pf[nt][1] = *(uint32_t*)&h23;
        }
        s0 += __shfl_xor_sync(0xffffffffu, s0, 1);
        s0 += __shfl_xor_sync(0xffffffffu, s0, 2);
        s1 += __shfl_xor_sync(0xffffffffu, s1, 1);
        s1 += __shfl_xor_sync(0xffffffffu, s1, 2);
        l0 = l0 * cr0 + s0;
        l1 = l1 * cr1 + s1;

        #pragma unroll
        for (int nt = 0; nt < 6; nt++) {
            oa[nt][0] *= cr0; oa[nt][1] *= cr0;
            oa[nt][2] *= cr1; oa[nt][3] *= cr1;
        }

        // O += P V
        const uint32_t vb0 = sVa + (uint32_t)buf * 7168u + voff;
        #pragma unroll
        for (int kt = 0; kt < 4; kt++) {
            uint32_t pa[4] = { pf[2 * kt][0], pf[2 * kt][1],
                               pf[2 * kt + 1][0], pf[2 * kt + 1][1] };
            uint32_t vb[3][4];
            #pragma unroll
            for (int q = 0; q < 3; q++)
                ldmatrix4t(vb[q], vb0 + kt * 16u * 112u + q * 32u);
            #pragma unroll
            for (int nt = 0; nt < 6; nt++)
                mma16816(oa[nt], pa, &vb[nt >> 1][(nt & 1) * 2]);
        }
        if (++buf >= 3) buf = 0;
    }

    const float inv0 = 1.0f / l0, inv1 = 1.0f / l1;
    const int gid = lid >> 2, tig = lid & 3;
    const int r0 = q0 + wid * 16 + gid;
    __half* op = o + (size_t)(b * HW) * CDIM + h * DH;
    #pragma unroll
    for (int nt = 0; nt < 6; nt++) {
        const int col = nt * 8 + tig * 2;
        __half2 h0 = __floats2half2_rn(oa[nt][0] * inv0, oa[nt][1] * inv0);
        __half2 h1 = __floats2half2_rn(oa[nt][2] * inv1, oa[nt][3] * inv1);
        *(__half2*)&op[(size_t)r0 * CDIM + col] = h0;
        *(__half2*)&op[(size_t)(r0 + 8) * CDIM + col] = h1;
    }
}

// ---------------- launch ----------------
extern "C" void kernel_launch(void* const* d_in, const int* in_sizes, int n_in,
                              void* d_out, int out_size)
{
    const float* x     = (const float*)d_in[0];
    const float* ln1_g = (const float*)d_in[1];
    const float* ln1_b = (const float*)d_in[2];
    const float* lna_g = (const float*)d_in[3];
    const float* lna_b = (const float*)d_in[4];
    const float* w_qkv = (const float*)d_in[5];
    const float* w_out = (const float*)d_in[6];
    const float* ln2_g = (const float*)d_in[7];
    const float* ln2_b = (const float*)d_in[8];
    const float* w1    = (const float*)d_in[9];
    const float* b1    = (const float*)d_in[10];
    const float* w2    = (const float*)d_in[11];
    const float* b2    = (const float*)d_in[12];
    float* out = (float*)d_out;

    float *t, *t2, *t3;
    __half *ah, *qkvh, *oh, *mh, *hh, *wqkvT, *woutT, *w1T, *w2T;
    cudaGetSymbolAddress((void**)&t,     g_t);
    cudaGetSymbolAddress((void**)&ah,    g_ah);
    cudaGetSymbolAddress((void**)&qkvh,  g_qkvh);
    cudaGetSymbolAddress((void**)&oh,    g_oh);
    cudaGetSymbolAddress((void**)&t2,    g_t2);
    cudaGetSymbolAddress((void**)&mh,    g_mh);
    cudaGetSymbolAddress((void**)&hh,    g_hh);
    cudaGetSymbolAddress((void**)&t3,    g_t3);
    cudaGetSymbolAddress((void**)&wqkvT, g_wqkvT);
    cudaGetSymbolAddress((void**)&woutT, g_woutT);
    cudaGetSymbolAddress((void**)&w1T,   g_w1T);
    cudaGetSymbolAddress((void**)&w2T,   g_w2T);

    cudaFuncSetAttribute(prep_ln_kernel, cudaFuncAttributeMaxDynamicSharedMemorySize, LNSMEM);
    cudaFuncSetAttribute(attn_mma, cudaFuncAttributeMaxDynamicSharedMemorySize, ATT_SMEM);

    // weights
    wprep_all_kernel<<<1728, dim3(32, 8)>>>(w_qkv, w_out, w1, w2, wqkvT, woutT, w1T, w2T);
    // fused NCHW->tokens + double pre-norm
    prep_ln_kernel<<<dim3(HW / 32, BATCH), 256, LNSMEM>>>(x, t, ah, ln1_g, ln1_b, lna_g, lna_b);
    // qkv = a @ w_qkv (fp16 out)
    hgemm_mma<<<dim3(D3 / 128, NTOK / 128), 256>>>(
        ah, wqkvT, nullptr, qkvh, nullptr, nullptr, D3, CDIM, 4);
    // flash attention
    attn_mma<<<dim3(BATCH * HEADS, HW / 128), 256, ATT_SMEM>>>(qkvh, oh);
    // t2 = t + o @ w_out
    hgemm_mma<<<dim3(CDIM / 128, NTOK / 128), 256>>>(
        oh, woutT, t2, nullptr, nullptr, t, CDIM, CDIM, 1);
    // m = LN2(t2)
    ln_kernel<<<NTOK, 128>>>(t2, mh, ln2_g, ln2_b);
    // h = gelu(m @ w1 + b1)
    hgemm_mma<<<dim3(DFF / 128, NTOK / 128), 256>>>(
        mh, w1T, nullptr, hh, b1, nullptr, DFF, CDIM, 2);
    // t3 = t2 + h @ w2 + b2
    hgemm_mma<<<dim3(CDIM / 128, NTOK / 128), 256>>>(
        hh, w2T, t3, nullptr, b2, t2, CDIM, DFF, 3);
    // tokens -> NCHW
    transpose_out_kernel<<<dim3(HW / 32, CDIM / 32, BATCH), dim3(32, 8)>>>(t3, out);
}